// round 6
// baseline (speedup 1.0000x reference)
#include <cuda_runtime.h>
#include <cuda_fp16.h>
#include <cstdint>

#define BB 4096
#define TT 512
#define IND 5
#define E 30
#define NH 3
#define HD 10
#define KSPLIT 8
#define KTILE 512   // 4096 / KSPLIT
#define RQ 4        // q rows per thread in attention

typedef unsigned long long u64;

// ---------------- scratch (device globals; no allocations allowed) ----------
__device__ float g_hn[BB * E];
__device__ float g_cn[BB * E];
__device__ float g_q[BB * E];
__device__ float g_k[BB * E];
__device__ float g_v[BB * E];
__device__ float g_psum[NH * KSPLIT * BB];
__device__ float g_pacc[NH * KSPLIT * BB * HD];

// ---------------- f32x2 helpers (attention kernel) ---------------------------
__device__ __forceinline__ u64 pack2(float lo, float hi) {
    u64 r; asm("mov.b64 %0, {%1, %2};" : "=l"(r) : "f"(lo), "f"(hi)); return r;
}
__device__ __forceinline__ u64 bcast2(float v) {
    u64 r; asm("mov.b64 %0, {%1, %1};" : "=l"(r) : "f"(v)); return r;
}
__device__ __forceinline__ void unpack2(u64 p, float& lo, float& hi) {
    asm("mov.b64 {%0, %1}, %2;" : "=f"(lo), "=f"(hi) : "l"(p));
}
__device__ __forceinline__ u64 ffma2(u64 a, u64 b, u64 c) {
    u64 d; asm("fma.rn.f32x2 %0, %1, %2, %3;" : "=l"(d) : "l"(a), "l"(b), "l"(c));
    return d;
}

// ---------------- activation helpers -----------------------------------------
__device__ __forceinline__ float tanh_fast(float x) {
    float y; asm("tanh.approx.f32 %0, %1;" : "=f"(y) : "f"(x)); return y;
}
__device__ __forceinline__ float sig_fast(float x) {
    return fmaf(0.5f, tanh_fast(0.5f * x), 0.5f);
}
__device__ __forceinline__ float warp_sum(float v) {
    #pragma unroll
    for (int o = 16; o > 0; o >>= 1) v += __shfl_xor_sync(0xffffffffu, v, o);
    return v;
}

// ---------------- LSTM via tensor cores (mma.sync m16n8k16 f16 -> f32) -------
// One warp = 16 batch rows. Gates[16,120] = A[16,48] * B[48,120] each step.
// A = [h(0:30) | x(30:35) | 1 (35) | 0 pad], fp16, staged in smem, ldmatrix.
// B = [W_hh^T; W_ih^T; bias] fp16, stationary in registers (96 u32).
// Accumulate fp32; c kept in fp32 registers; activations tanh.approx.

#define AST 56          // A tile padded col stride (halves)
#define GST 132         // gate buffer padded col stride (floats)

__device__ __forceinline__ float bsrc(int k, int gn,
    const float* __restrict__ w_hh, const float* __restrict__ w_ih,
    const float* __restrict__ b_ih, const float* __restrict__ b_hh)
{
    if (gn >= 4 * E) return 0.0f;
    if (k < E)       return __ldg(w_hh + gn * E + k);
    if (k < E + IND) return __ldg(w_ih + gn * IND + (k - E));
    if (k == E + IND) return __ldg(b_ih + gn) + __ldg(b_hh + gn);
    return 0.0f;
}

__global__ __launch_bounds__(64, 1) void lstm_mma_kernel(
    const float* __restrict__ input, const float* __restrict__ w_ih,
    const float* __restrict__ w_hh, const float* __restrict__ b_ih,
    const float* __restrict__ b_hh)
{
    __shared__ __align__(16) __half Atile[2][16][AST];
    __shared__ __align__(16) float  gbuf[2][16][GST];

    const int wl   = threadIdx.x >> 5;
    const int lane = threadIdx.x & 31;
    const int r0   = (blockIdx.x * 2 + wl) * 16;     // first batch row of warp

    const int g  = lane >> 2;       // mma group id (0..7)
    const int iq = lane & 3;        // thread in group (0..3)

    // ---- stationary B fragments: breg[kc][nt][2] ----
    uint32_t breg[3][16][2];
    #pragma unroll
    for (int kc = 0; kc < 3; kc++) {
        #pragma unroll
        for (int nt = 0; nt < 16; nt++) {
            int gn = nt * 8 + g;
            int kb = kc * 16 + 2 * iq;
            __half2 h0 = __halves2half2(
                __float2half_rn(bsrc(kb,     gn, w_hh, w_ih, b_ih, b_hh)),
                __float2half_rn(bsrc(kb + 1, gn, w_hh, w_ih, b_ih, b_hh)));
            __half2 h1 = __halves2half2(
                __float2half_rn(bsrc(kb + 8, gn, w_hh, w_ih, b_ih, b_hh)),
                __float2half_rn(bsrc(kb + 9, gn, w_hh, w_ih, b_ih, b_hh)));
            breg[kc][nt][0] = *reinterpret_cast<uint32_t*>(&h0);
            breg[kc][nt][1] = *reinterpret_cast<uint32_t*>(&h1);
        }
    }

    // ---- init A tile: zeros, col 35 = 1.0 ----
    for (int i = lane; i < 16 * AST; i += 32)
        ((__half*)Atile[wl])[i] = __float2half(0.0f);
    __syncwarp();
    if (lane < 16) Atile[wl][lane][E + IND] = __float2half(1.0f);

    // ---- x streams: thread handles up to 3 of the 80 per-step x values ----
    const float* xptr[3];
    __half* xdst[3];
    bool xok[3];
    float xn[3];
    #pragma unroll
    for (int k = 0; k < 3; k++) {
        int p = lane + 32 * k;
        xok[k] = (p < 16 * IND);
        int rr = xok[k] ? (p / IND) : 0;
        int jj = xok[k] ? (p % IND) : 0;
        xptr[k] = input + (size_t)(r0 + rr) * TT * IND + jj;
        xdst[k] = &Atile[wl][rr][E + jj];
        xn[k] = xok[k] ? __ldg(xptr[k]) : 0.0f;     // x[t=0]
    }

    // ---- epilogue mapping: lane -> row (lane>>1), units 15*(lane&1)+k ----
    const int erow = lane >> 1;
    const int ubase = 15 * (lane & 1);
    float cc[15];
    #pragma unroll
    for (int k = 0; k < 15; k++) cc[k] = 0.0f;

    // ldmatrix source address for this lane (per k-chunk)
    const int lrow = lane & 15;
    const int lcol8 = (lane & 16) ? 8 : 0;

    for (int t = 0; t < TT; t++) {
        // stage x[t] into A tile; prefetch x[t+1]
        #pragma unroll
        for (int k = 0; k < 3; k++)
            if (xok[k]) *xdst[k] = __float2half(xn[k]);
        if (t + 1 < TT) {
            #pragma unroll
            for (int k = 0; k < 3; k++) {
                xptr[k] += IND;
                if (xok[k]) xn[k] = __ldg(xptr[k]);
            }
        }
        __syncwarp();

        // gates = A * B
        float d[16][4];
        #pragma unroll
        for (int nt = 0; nt < 16; nt++) {
            d[nt][0] = 0.f; d[nt][1] = 0.f; d[nt][2] = 0.f; d[nt][3] = 0.f;
        }
        #pragma unroll
        for (int kc = 0; kc < 3; kc++) {
            uint32_t a0, a1, a2, a3;
            uint32_t saddr = (uint32_t)__cvta_generic_to_shared(
                &Atile[wl][lrow][kc * 16 + lcol8]);
            asm volatile(
                "ldmatrix.sync.aligned.m8n8.x4.shared.b16 {%0,%1,%2,%3}, [%4];"
                : "=r"(a0), "=r"(a1), "=r"(a2), "=r"(a3) : "r"(saddr));
            #pragma unroll
            for (int nt = 0; nt < 16; nt++) {
                asm volatile(
                    "mma.sync.aligned.m16n8k16.row.col.f32.f16.f16.f32 "
                    "{%0,%1,%2,%3}, {%4,%5,%6,%7}, {%8,%9}, {%0,%1,%2,%3};"
                    : "+f"(d[nt][0]), "+f"(d[nt][1]), "+f"(d[nt][2]), "+f"(d[nt][3])
                    : "r"(a0), "r"(a1), "r"(a2), "r"(a3),
                      "r"(breg[kc][nt][0]), "r"(breg[kc][nt][1]));
            }
        }

        // scatter D to gate buffer
        #pragma unroll
        for (int nt = 0; nt < 16; nt++) {
            int c0 = nt * 8 + 2 * iq;
            *(float2*)&gbuf[wl][g][c0]     = make_float2(d[nt][0], d[nt][1]);
            *(float2*)&gbuf[wl][g + 8][c0] = make_float2(d[nt][2], d[nt][3]);
        }
        __syncwarp();

        // activations + state update for 15 (row,unit) pairs
        const float* gr = gbuf[wl][erow];
        if (t + 1 < TT) {
            #pragma unroll
            for (int k = 0; k < 15; k++) {
                int u = ubase + k;
                float ig = sig_fast(gr[u]);
                float fg = sig_fast(gr[E + u]);
                float gg = tanh_fast(gr[2 * E + u]);
                float og = sig_fast(gr[3 * E + u]);
                cc[k] = fmaf(fg, cc[k], ig * gg);
                float h = og * tanh_fast(cc[k]);
                Atile[wl][erow][u] = __float2half(h);
            }
        } else {
            #pragma unroll
            for (int k = 0; k < 15; k++) {
                int u = ubase + k;
                float ig = sig_fast(gr[u]);
                float fg = sig_fast(gr[E + u]);
                float gg = tanh_fast(gr[2 * E + u]);
                float og = sig_fast(gr[3 * E + u]);
                cc[k] = fmaf(fg, cc[k], ig * gg);
                float h = og * tanh_fast(cc[k]);
                g_hn[(size_t)(r0 + erow) * E + u] = h;
                g_cn[(size_t)(r0 + erow) * E + u] = cc[k];
            }
        }
        __syncwarp();
    }
}

// ---------------- kernel 2: QKV projections (warp per row) --------------------
__global__ __launch_bounds__(256) void qkv_kernel(
    const float* __restrict__ ipw, const float* __restrict__ ipb)
{
    int warp = (blockIdx.x * blockDim.x + threadIdx.x) >> 5;
    int lane = threadIdx.x & 31;
    bool act = lane < E;
    int li = act ? lane : 0;

    float h = g_hn[(size_t)warp * E + li];
    float c = g_cn[(size_t)warp * E + li];
    float aq = __ldg(ipb + 0 * E + li);
    float ak = __ldg(ipb + 1 * E + li);
    float av = __ldg(ipb + 2 * E + li);
    #pragma unroll
    for (int j = 0; j < E; j++) {
        float hj = __shfl_sync(0xffffffffu, h, j);
        float cj = __shfl_sync(0xffffffffu, c, j);
        aq = fmaf(__ldg(ipw + (0 * E + li) * E + j), hj, aq);
        ak = fmaf(__ldg(ipw + (1 * E + li) * E + j), cj, ak);
        av = fmaf(__ldg(ipw + (2 * E + li) * E + j), cj, av);
    }
    if (act) {
        g_q[(size_t)warp * E + lane] = aq;
        g_k[(size_t)warp * E + lane] = ak;
        g_v[(size_t)warp * E + lane] = av;
    }
}

// ---------------- kernel 3: attention partials (flash-style, no-max) ----------
__global__ __launch_bounds__(128) void attn_kernel()
{
    __shared__ u64 ks2[KTILE * 5];
    __shared__ u64 vs2[KTILE * 5];
    int h   = blockIdx.z;
    int ksp = blockIdx.y;
    int qc  = blockIdx.x;
    int tid = threadIdx.x;
    int k0  = ksp * KTILE;

    for (int i = tid; i < KTILE * 5; i += 128) {
        int m = i / 5, p = i - m * 5;
        const float2* kp = (const float2*)(g_k + (size_t)(k0 + m) * E + h * HD) + p;
        const float2* vp = (const float2*)(g_v + (size_t)(k0 + m) * E + h * HD) + p;
        float2 kv = *kp; float2 vv = *vp;
        ks2[i] = pack2(kv.x, kv.y);
        vs2[i] = pack2(vv.x, vv.y);
    }
    __syncthreads();

    int q0 = qc * (128 * RQ) + tid * RQ;

    u64 qp[RQ][5], accp[RQ][5];
    float s[RQ];
    #pragma unroll
    for (int r = 0; r < RQ; r++) {
        s[r] = 0.0f;
        #pragma unroll
        for (int p = 0; p < 5; p++) {
            float2 t = *((const float2*)(g_q + (size_t)(q0 + r) * E + h * HD) + p);
            qp[r][p] = pack2(t.x * 0.3162277660168379f, t.y * 0.3162277660168379f);
            accp[r][p] = pack2(0.0f, 0.0f);
        }
    }

    for (int m = 0; m < KTILE; m++) {
        u64 kk[5], vv[5];
        #pragma unroll
        for (int p = 0; p < 5; p++) { kk[p] = ks2[m * 5 + p]; vv[p] = vs2[m * 5 + p]; }
        #pragma unroll
        for (int r = 0; r < RQ; r++) {
            u64 d2 = pack2(0.0f, 0.0f);
            #pragma unroll
            for (int p = 0; p < 5; p++) d2 = ffma2(qp[r][p], kk[p], d2);
            float lo, hi; unpack2(d2, lo, hi);
            float pr = __expf(lo + hi);
            s[r] += pr;
            u64 p2 = bcast2(pr);
            #pragma unroll
            for (int p = 0; p < 5; p++) accp[r][p] = ffma2(p2, vv[p], accp[r][p]);
        }
    }

    #pragma unroll
    for (int r = 0; r < RQ; r++) {
        int base = (h * KSPLIT + ksp) * BB + (q0 + r);
        g_psum[base] = s[r];
        #pragma unroll
        for (int p = 0; p < 5; p++) {
            float lo, hi; unpack2(accp[r][p], lo, hi);
            g_pacc[(size_t)base * HD + 2 * p]     = lo;
            g_pacc[(size_t)base * HD + 2 * p + 1] = hi;
        }
    }
}

// ---------------- kernel 4: combine + out_proj + LN + MLP + LN + head --------
__global__ __launch_bounds__(256) void epi_kernel(
    const float* __restrict__ opw, const float* __restrict__ opb,
    const float* __restrict__ f1w, const float* __restrict__ f1b,
    const float* __restrict__ f2w, const float* __restrict__ f2b,
    const float* __restrict__ lng, const float* __restrict__ lnb,
    const float* __restrict__ ow,  const float* __restrict__ ob,
    float* __restrict__ out)
{
    int warp = (blockIdx.x * blockDim.x + threadIdx.x) >> 5;
    int lane = threadIdx.x & 31;
    bool act = lane < E;
    int li = act ? lane : 0;
    int hh = li / HD, dd = li - hh * HD;

    // combine split-softmax partials
    float num = 0.0f, den = 0.0f;
    #pragma unroll
    for (int ksp = 0; ksp < KSPLIT; ksp++) {
        int base = (hh * KSPLIT + ksp) * BB + warp;
        num += g_pacc[(size_t)base * HD + dd];
        den += g_psum[base];
    }
    float ctx = __fdividef(num, den);

    // out_proj
    float ao = __ldg(opb + li);
    #pragma unroll
    for (int j = 0; j < E; j++) {
        float cj = __shfl_sync(0xffffffffu, ctx, j);
        ao = fmaf(__ldg(opw + li * E + j), cj, ao);
    }
    float r1 = ao + g_hn[(size_t)warp * E + li];

    // LN1
    float lg = __ldg(lng + li), lb = __ldg(lnb + li);
    float mu = warp_sum(act ? r1 : 0.0f) * (1.0f / E);
    float dv = act ? (r1 - mu) : 0.0f;
    float var = warp_sum(dv * dv) * (1.0f / E);
    float x1 = fmaf(dv * rsqrtf(var + 1e-5f), lg, lb);
    if (!act) x1 = 0.0f;

    // fc1 + exact GELU
    float y = __ldg(f1b + li);
    #pragma unroll
    for (int j = 0; j < E; j++) {
        float xj = __shfl_sync(0xffffffffu, x1, j);
        y = fmaf(__ldg(f1w + li * E + j), xj, y);
    }
    float gy = 0.5f * y * (1.0f + erff(y * 0.7071067811865475f));

    // fc2
    float z = __ldg(f2b + li);
    #pragma unroll
    for (int j = 0; j < E; j++) {
        float gj = __shfl_sync(0xffffffffu, gy, j);
        z = fmaf(__ldg(f2w + li * E + j), gj, z);
    }
    float r2 = x1 + z;

    // LN2
    float mu2 = warp_sum(act ? r2 : 0.0f) * (1.0f / E);
    float dv2 = act ? (r2 - mu2) : 0.0f;
    float var2 = warp_sum(dv2 * dv2) * (1.0f / E);
    float x2 = fmaf(dv2 * rsqrtf(var2 + 1e-5f), lg, lb);
    if (!act) x2 = 0.0f;

    // final head [E -> 3]
    float o0 = __ldg(ob + 0), o1 = __ldg(ob + 1), o2 = __ldg(ob + 2);
    #pragma unroll
    for (int j = 0; j < E; j++) {
        float xj = __shfl_sync(0xffffffffu, x2, j);
        o0 = fmaf(__ldg(ow + 0 * E + j), xj, o0);
        o1 = fmaf(__ldg(ow + 1 * E + j), xj, o1);
        o2 = fmaf(__ldg(ow + 2 * E + j), xj, o2);
    }
    if (lane == 0) {
        out[(size_t)warp * 3 + 0] = o0;
        out[(size_t)warp * 3 + 1] = o1;
        out[(size_t)warp * 3 + 2] = o2;
    }
}

// ---------------- launch ------------------------------------------------------
extern "C" void kernel_launch(void* const* d_in, const int* in_sizes, int n_in,
                              void* d_out, int out_size)
{
    const float* input = (const float*)d_in[0];   // [4096,512,5]
    const float* w_ih  = (const float*)d_in[1];   // [120,5]
    const float* w_hh  = (const float*)d_in[2];   // [120,30]
    const float* b_ih  = (const float*)d_in[3];   // [120]
    const float* b_hh  = (const float*)d_in[4];   // [120]
    const float* ipw   = (const float*)d_in[5];   // [90,30]
    const float* ipb   = (const float*)d_in[6];   // [90]
    const float* opw   = (const float*)d_in[7];   // [30,30]
    const float* opb   = (const float*)d_in[8];   // [30]
    const float* f1w   = (const float*)d_in[9];   // [30,30]
    const float* f1b   = (const float*)d_in[10];  // [30]
    const float* f2w   = (const float*)d_in[11];  // [30,30]
    const float* f2b   = (const float*)d_in[12];  // [30]
    const float* lng   = (const float*)d_in[13];  // [30]
    const float* lnb   = (const float*)d_in[14];  // [30]
    const float* ow    = (const float*)d_in[15];  // [3,30]
    const float* ob    = (const float*)d_in[16];  // [3]
    float* out = (float*)d_out;

    lstm_mma_kernel<<<BB / 32, 64>>>(input, w_ih, w_hh, b_ih, b_hh);
    qkv_kernel<<<BB / 8, 256>>>(ipw, ipb);
    attn_kernel<<<dim3(BB / (128 * RQ), KSPLIT, NH), 128>>>();
    epi_kernel<<<BB / 8, 256>>>(opw, opb, f1w, f1b, f2w, f2b, lng, lnb, ow, ob, out);
}